// round 15
// baseline (speedup 1.0000x reference)
#include <cuda_runtime.h>
#include <cuda_bf16.h>

#define H    128
#define FF   8
#define MB   14
#define NT   512
#define BB   2048
#define L2E  1.4426950408889634f

typedef unsigned long long u64;
typedef unsigned int u32;
typedef unsigned short u16;

// A fragments, m16n8k16 layout: [phase][(wm*8+kc)*4+g][lane] uint4
// A row = g*128 + wm*16 + r  (gate-aligned M tiling)
__device__ __align__(16) uint4 g_AFhi[2 * 8192];
__device__ __align__(16) uint4 g_AFlo[2 * 8192];

// ---- dyn smem byte offsets ----
#define SAF 0          // A_hi fragments (131072)
#define SBF 131072     // B fragments: [buf][hl][kc][lane] uint4 (16384)
#define SW  147456     // W blocked [f][m][g] f32 (16384)
#define SWO 163840     // W_out (4096)
#define SHS 167936     // h fp32 [j][18] decoder staging (9216)
#define SX  177152     // x double buffer 2 x (8f x 16n) f32 (1024)
#define SY  178176     // y staging (512)
#define SMEM_BYTES 178688

__device__ __forceinline__ float ex2f(float x){ float r; asm("ex2.approx.f32 %0, %1;" : "=f"(r) : "f"(x)); return r; }
__device__ __forceinline__ float rcpf(float x){ float r; asm("rcp.approx.f32 %0, %1;" : "=f"(r) : "f"(x)); return r; }
__device__ __forceinline__ u16 bf16bits(float v) {
    __nv_bfloat16 h = __float2bfloat16(v); return *(u16*)&h;
}
__device__ __forceinline__ float bf16val(u16 b) {
    __nv_bfloat16 h = *(__nv_bfloat16*)&b; return __bfloat162float(h);
}

// D += A(16x16 bf16) x B(16x8 bf16), fp32 accum — base ISA
__device__ __forceinline__ void mma16816(float* d, uint4 a, u32 b0, u32 b1) {
    asm volatile("mma.sync.aligned.m16n8k16.row.col.f32.bf16.bf16.f32 "
        "{%0,%1,%2,%3}, {%4,%5,%6,%7}, {%8,%9}, {%0,%1,%2,%3};"
        : "+f"(d[0]), "+f"(d[1]), "+f"(d[2]), "+f"(d[3])
        : "r"(a.x), "r"(a.y), "r"(a.z), "r"(a.w), "r"(b0), "r"(b1));
}

// ---- prep: A fragments (hi/lo bf16 split of U^T), gate-aligned tiling ----
__global__ void prep_kernel(const float* __restrict__ Ue, const float* __restrict__ Ud) {
    int i = blockIdx.x * blockDim.x + threadIdx.x;
    if (i >= 16384) return;
    int p = i >> 13, idx = i & 8191;
    int lane = idx & 31, g = (idx >> 5) & 3, kc = (idx >> 7) & 7, w = idx >> 10;
    const float* U = p ? Ud : Ue;
    int r0 = lane >> 2, kb = kc * 16 + (lane & 3) * 2;
    int c0 = g * 128 + w * 16 + r0;
    int ks[4] = { kb, kb, kb + 8, kb + 8 };
    int cs[4] = { c0, c0 + 8, c0, c0 + 8 };
    u32 hi[4], lo[4];
    #pragma unroll
    for (int q = 0; q < 4; q++) {
        float v0 = U[ks[q] * 512 + cs[q]];
        float v1 = U[(ks[q] + 1) * 512 + cs[q]];
        u16 h0 = bf16bits(v0), h1 = bf16bits(v1);
        u16 l0 = bf16bits(v0 - bf16val(h0));
        u16 l1 = bf16bits(v1 - bf16val(h1));
        hi[q] = (u32)h0 | ((u32)h1 << 16);
        lo[q] = (u32)l0 | ((u32)l1 << 16);
    }
    g_AFhi[p * 8192 + idx] = make_uint4(hi[0], hi[1], hi[2], hi[3]);
    g_AFlo[p * 8192 + idx] = make_uint4(lo[0], lo[1], lo[2], lo[3]);
}

__global__ void __launch_bounds__(NT, 1)
lstm_mma_kernel(const float* __restrict__ x,
                const float* __restrict__ We, const float* __restrict__ be,
                const float* __restrict__ Wd, const float* __restrict__ bd,
                const float* __restrict__ Wo, const float* __restrict__ bog,
                float* __restrict__ out, int T)
{
    extern __shared__ __align__(16) char sm[];
    uint4* afh = (uint4*)(sm + SAF);
    const u64* bfl = (const u64*)(sm + SBF);
    u16*   bfu = (u16*)(sm + SBF);
    float* wsm = (float*)(sm + SW);
    float* wosm = (float*)(sm + SWO);
    float* hsm = (float*)(sm + SHS);
    float* xsm = (float*)(sm + SX);
    float* ysm = (float*)(sm + SY);

    const int tid  = threadIdx.x;
    const int wp   = tid >> 5, lane = tid & 31;
    const int ws   = wp >> 3;                 // warp set: n-cols [ws*8, ws*8+8)
    const int wm   = wp & 7;                  // m-warp: units [wm*16, wm*16+16)
    const int rs   = blockIdx.x * MB;
    const int j0   = wm * 16 + (lane >> 2);   // unit for d regs q0,q1 (q2,q3 -> j0+8)
    const int cb   = ws * 8 + (lane & 3) * 2; // base batch-col

    const int  xm = tid >> 3, xf = tid & 7;
    const bool xth = tid < MB * FF;           // warps 0-3 (set 0) only
    const bool gx  = xth && (rs + xm < BB);
    const float bof = bog[xf];
    const float* xrow = x   + (size_t)(rs + xm) * T * FF + xf;
    float*       orow = out + (size_t)(rs + xm) * T * FF + xf;

    for (int i = tid; i < 4096; i += NT) ((u32*)(sm + SBF))[i] = 0;   // B (h0 = 0)
    for (int i = tid; i < 384; i += NT) xsm[i] = 0.f;                 // xsm + ysm
    for (int i = tid; i < H * FF; i += NT) wosm[i] = Wo[i];
    if (gx) xsm[xf * 16 + xm] = xrow[0];

    float cst[4];
    #pragma unroll
    for (int q = 0; q < 4; q++) cst[q] = 0.f;
    int buf = 0;

    for (int phase = 0; phase < 2; phase++) {
        const bool dec = (phase == 1);
        const uint4* gafh = g_AFhi + phase * 8192;
        const uint4* gafl = g_AFlo + phase * 8192;
        const float* Wm = dec ? Wd : We;
        const float* bv = dec ? bd : be;

        for (int i = tid; i < 8192; i += NT) afh[i] = gafh[i];        // A_hi -> smem
        for (int i = tid; i < 4096; i += NT) {                        // W [f][m][g]
            int f = i >> 9, c = i & 511;
            wsm[((f << 7) + (c & 127)) * 4 + (c >> 7)] = Wm[i];
        }
        float bgv[2][4];
        #pragma unroll
        for (int u = 0; u < 2; u++)
            #pragma unroll
            for (int g = 0; g < 4; g++) bgv[u][g] = bv[g * H + j0 + u * 8];
        if (dec && gx) ysm[xf * 16 + xm] = xrow[(size_t)(T - 1) * FF];  // y0
        __syncthreads();

        for (int t = 0; t < T; t++) {
            // ---- x@W + bias (exact fp32), 2 units x 2 cols ----
            const float* xb = dec ? ysm : (xsm + (t & 1) * 128);
            float xw[4][4];                        // [g][q]
            #pragma unroll
            for (int g = 0; g < 4; g++)
                #pragma unroll
                for (int q = 0; q < 4; q++) xw[g][q] = bgv[q >> 1][g];
            #pragma unroll
            for (int f = 0; f < FF; f++) {
                float4 w0 = ((const float4*)wsm)[f * 128 + j0];
                float4 w1 = ((const float4*)wsm)[f * 128 + j0 + 8];
                float x0 = xb[f * 16 + cb], x1 = xb[f * 16 + cb + 1];
                xw[0][0] = fmaf(x0, w0.x, xw[0][0]); xw[0][1] = fmaf(x1, w0.x, xw[0][1]);
                xw[1][0] = fmaf(x0, w0.y, xw[1][0]); xw[1][1] = fmaf(x1, w0.y, xw[1][1]);
                xw[2][0] = fmaf(x0, w0.z, xw[2][0]); xw[2][1] = fmaf(x1, w0.z, xw[2][1]);
                xw[3][0] = fmaf(x0, w0.w, xw[3][0]); xw[3][1] = fmaf(x1, w0.w, xw[3][1]);
                xw[0][2] = fmaf(x0, w1.x, xw[0][2]); xw[0][3] = fmaf(x1, w1.x, xw[0][3]);
                xw[1][2] = fmaf(x0, w1.y, xw[1][2]); xw[1][3] = fmaf(x1, w1.y, xw[1][3]);
                xw[2][2] = fmaf(x0, w1.z, xw[2][2]); xw[2][3] = fmaf(x1, w1.z, xw[2][3]);
                xw[3][2] = fmaf(x0, w1.w, xw[3][2]); xw[3][3] = fmaf(x1, w1.w, xw[3][3]);
            }

            // ---- z = U^T h: 96 HMMA/warp (one n-tile), D in regs ----
            float d[4][4];
            #pragma unroll
            for (int g = 0; g < 4; g++)
                #pragma unroll
                for (int q = 0; q < 4; q++) d[g][q] = 0.f;

            uint4 alo[4], alon[4];
            #pragma unroll
            for (int g = 0; g < 4; g++) alo[g] = gafl[((wm * 8) * 4 + g) * 32 + lane];

            #pragma unroll
            for (int kc = 0; kc < 8; kc++) {
                u64 bh = bfl[((((buf * 2 + 0) * 8 + kc) * 32 + lane) << 1) + ws];
                u64 bl = bfl[((((buf * 2 + 1) * 8 + kc) * 32 + lane) << 1) + ws];
                u32 bh0 = (u32)bh, bh1 = (u32)(bh >> 32);
                u32 bl0 = (u32)bl, bl1 = (u32)(bl >> 32);
                if (kc < 7) {
                    #pragma unroll
                    for (int g = 0; g < 4; g++)
                        alon[g] = gafl[((wm * 8 + kc + 1) * 4 + g) * 32 + lane];
                }
                #pragma unroll
                for (int g = 0; g < 4; g++) {
                    uint4 ah = afh[((wm * 8 + kc) * 4 + g) * 32 + lane];
                    mma16816(d[g], ah, bh0, bh1);        // Uhi * hhi
                    mma16816(d[g], ah, bl0, bl1);        // Uhi * hlo
                    mma16816(d[g], alo[g], bh0, bh1);    // Ulo * hhi
                }
                #pragma unroll
                for (int g = 0; g < 4; g++) alo[g] = alon[g];
            }

            // ---- gates from accumulators; scatter h into B(nbuf) ----
            const int nbuf = buf ^ 1;
            #pragma unroll
            for (int q = 0; q < 4; q++) {
                const int u = q >> 1, off = q & 1;
                const int j = j0 + u * 8;
                const int n = cb + off;
                float zi = d[0][q] + xw[0][q];
                float zf = d[1][q] + xw[1][q];
                float zg = d[2][q] + xw[2][q];
                float zo = d[3][q] + xw[3][q];
                float di = 1.f + ex2f(-L2E * zi);
                float df = 1.f + ex2f(-L2E * zf);
                float r  = rcpf(di * df);
                float si = r * df, sf = r * di;
                float dg = 1.f + ex2f(2.f * L2E * zg);
                float dd = 1.f + ex2f(-L2E * zo);
                float r2 = rcpf(dg * dd);
                float tg = fmaf(-2.f, r2 * dd, 1.f);
                float so = r2 * dg;
                float cn = fmaf(sf, cst[q], si * tg);
                cst[q] = cn;
                float dc = 1.f + ex2f(2.f * L2E * cn);
                float hv = so * fmaf(-2.f, rcpf(dc), 1.f);
                if (n < MB) {
                    const int kk = j & 15;
                    const int tb = (kk >> 1) & 3, regB = kk >> 3, bitB = kk & 1;
                    const int laneB = (n & 7) * 4 + tb, ntB = n >> 3;
                    u16 hb = bf16bits(hv);
                    u16 lb = bf16bits(hv - bf16val(hb));
                    bfu[((((nbuf * 2 + 0) * 8 + wm) * 32 + laneB) << 3) + ((ntB * 2 + regB) << 1) + bitB] = hb;
                    bfu[((((nbuf * 2 + 1) * 8 + wm) * 32 + laneB) << 3) + ((ntB * 2 + regB) << 1) + bitB] = lb;
                    if (dec) hsm[j * 18 + n] = hv;
                }
            }

            if (!dec) {
                if (gx && t + 1 < T)    // prefetch next x into other slot
                    xsm[((t + 1) & 1) * 128 + xf * 16 + xm] = xrow[(size_t)(t + 1) * FF];
            } else {
                __syncthreads();        // hsm complete
                if (xth) {
                    float a = 0.f, b2 = 0.f;
                    #pragma unroll 8
                    for (int k = 0; k < H; k += 2) {
                        a  = fmaf(hsm[(k    ) * 18 + xm], wosm[(k    ) * FF + xf], a);
                        b2 = fmaf(hsm[(k + 1) * 18 + xm], wosm[(k + 1) * FF + xf], b2);
                    }
                    float y = fmaxf(bof + a + b2, 0.f);
                    ysm[xf * 16 + xm] = y;
                    if (gx) orow[(size_t)t * FF] = y;
                }
            }
            __syncthreads();            // B(nbuf) / x / y ready for next step
            buf ^= 1;
        }
    }
}

extern "C" void kernel_launch(void* const* d_in, const int* in_sizes, int n_in,
                              void* d_out, int out_size)
{
    const float* x  = (const float*)d_in[0];
    const float* We = (const float*)d_in[1];
    const float* Ue = (const float*)d_in[2];
    const float* be = (const float*)d_in[3];
    const float* Wd = (const float*)d_in[4];
    const float* Ud = (const float*)d_in[5];
    const float* bd = (const float*)d_in[6];
    const float* Wo = (const float*)d_in[7];
    const float* bo = (const float*)d_in[8];
    float* out = (float*)d_out;

    const int T = in_sizes[0] / (BB * FF);

    prep_kernel<<<64, 256>>>(Ue, Ud);

    cudaFuncSetAttribute(lstm_mma_kernel,
                         cudaFuncAttributeMaxDynamicSharedMemorySize, SMEM_BYTES);
    lstm_mma_kernel<<<(BB + MB - 1) / MB, NT, SMEM_BYTES>>>(x, We, be, Wd, bd, Wo, bo, out, T);
}

// round 17
// speedup vs baseline: 1.2696x; 1.2696x over previous
#include <cuda_runtime.h>
#include <cuda_bf16.h>

#define H    128
#define FF   8
#define MB   14
#define NT   256
#define BB   2048
#define NKC  9      // 8 h-chunks + 1 fused x/bias chunk
#define L2E  1.4426950408889634f

typedef unsigned long long u64;
typedef unsigned int u32;
typedef unsigned short u16;

// A fragments, m16n8k16: [phase][(w*NKC+kc)*4+g][lane] uint4
// kc<8: U rows; kc=8: W rows 0-7, bias pair rows 8-9, zeros 10-15.
__device__ __align__(16) uint4 g_AFhi[2 * 9216];
__device__ __align__(16) uint4 g_AFlo[2 * 9216];

// ---- dyn smem byte offsets ----
#define SAF 0          // A_hi fragments (147456)
#define SBF 147456     // B fragments: [buf][hl][kc][lane] uint4 (18432)
#define SWO 165888     // W_out (4096)
#define SHS 169984     // h fp32 [j][18] decoder staging (9216)
#define SMEM_BYTES 179200

__device__ __forceinline__ float ex2f(float x){ float r; asm("ex2.approx.f32 %0, %1;" : "=f"(r) : "f"(x)); return r; }
__device__ __forceinline__ float rcpf(float x){ float r; asm("rcp.approx.f32 %0, %1;" : "=f"(r) : "f"(x)); return r; }
__device__ __forceinline__ u16 bf16bits(float v) {
    __nv_bfloat16 h = __float2bfloat16(v); return *(u16*)&h;
}
__device__ __forceinline__ float bf16val(u16 b) {
    __nv_bfloat16 h = *(__nv_bfloat16*)&b; return __bfloat162float(h);
}

__device__ __forceinline__ void mma16816(float* d, uint4 a, u32 b0, u32 b1) {
    asm volatile("mma.sync.aligned.m16n8k16.row.col.f32.bf16.bf16.f32 "
        "{%0,%1,%2,%3}, {%4,%5,%6,%7}, {%8,%9}, {%0,%1,%2,%3};"
        : "+f"(d[0]), "+f"(d[1]), "+f"(d[2]), "+f"(d[3])
        : "r"(a.x), "r"(a.y), "r"(a.z), "r"(a.w), "r"(b0), "r"(b1));
}

// u16 index of B-fragment slot (k = row within chunk, n = batch col)
__device__ __forceinline__ int bslot(int bufhl, int kc, int k, int n) {
    int tb = (k >> 1) & 3, regB = (k >> 3) & 1, bitB = k & 1;
    int laneB = (n & 7) * 4 + tb, ntB = n >> 3;
    return (((bufhl * NKC + kc) * 32 + laneB) << 3) + ((ntB * 2 + regB) << 1) + bitB;
}
__device__ __forceinline__ void write_x(u16* bfu, int buf, int k, int n, float v) {
    u16 hb = bf16bits(v);
    bfu[bslot(buf * 2 + 0, 8, k, n)] = hb;
    bfu[bslot(buf * 2 + 1, 8, k, n)] = bf16bits(v - bf16val(hb));
}

// ---- prep: A fragments, hi/lo bf16 split of [U; W; b] ----
__global__ void prep_kernel(const float* __restrict__ Ue, const float* __restrict__ Ud,
                            const float* __restrict__ We, const float* __restrict__ Wd,
                            const float* __restrict__ be, const float* __restrict__ bd)
{
    int i = blockIdx.x * blockDim.x + threadIdx.x;
    if (i >= 2 * 9216) return;
    int p = i / 9216, idx = i % 9216;
    int lane = idx & 31, tt = idx >> 5;
    int g = tt & 3; tt >>= 2;
    int kc = tt % NKC, w = tt / NKC;
    const float* U = p ? Ud : Ue;
    const float* W = p ? Wd : We;
    const float* b = p ? bd : be;
    int r0 = lane >> 2, kb = (lane & 3) * 2;
    int c0 = g * 128 + w * 16 + r0;
    int ks[4] = { kb, kb, kb + 8, kb + 8 };
    int cs[4] = { c0, c0 + 8, c0, c0 + 8 };
    u32 hi[4], lo[4];
    #pragma unroll
    for (int q = 0; q < 4; q++) {
        u16 h2[2], l2[2];
        #pragma unroll
        for (int e = 0; e < 2; e++) {
            int row = ks[q] + e, c = cs[q];
            if (kc < 8) {
                float v = U[(kc * 16 + row) * 512 + c];
                u16 hb = bf16bits(v);
                h2[e] = hb; l2[e] = bf16bits(v - bf16val(hb));
                continue;
            }
            if (row < 8) {
                float v = W[row * 512 + c];
                u16 hb = bf16bits(v);
                h2[e] = hb; l2[e] = bf16bits(v - bf16val(hb));
            } else if (row == 8) {
                h2[e] = bf16bits(b[c]); l2[e] = 0;
            } else if (row == 9) {
                float v = b[c];
                u16 hb = bf16bits(v);
                h2[e] = bf16bits(v - bf16val(hb)); l2[e] = 0;  // bias-lo rides in A_hi
            } else {
                h2[e] = 0; l2[e] = 0;
            }
        }
        hi[q] = (u32)h2[0] | ((u32)h2[1] << 16);
        lo[q] = (u32)l2[0] | ((u32)l2[1] << 16);
    }
    g_AFhi[p * 9216 + idx] = make_uint4(hi[0], hi[1], hi[2], hi[3]);
    g_AFlo[p * 9216 + idx] = make_uint4(lo[0], lo[1], lo[2], lo[3]);
}

__global__ void __launch_bounds__(NT, 1)
lstm_mma_kernel(const float* __restrict__ x,
                const float* __restrict__ Wo, const float* __restrict__ bog,
                float* __restrict__ out, int T)
{
    extern __shared__ __align__(16) char sm[];
    uint4* afh = (uint4*)(sm + SAF);
    uint4* bfr = (uint4*)(sm + SBF);
    u16*   bfu = (u16*)(sm + SBF);
    float* wosm = (float*)(sm + SWO);
    float* hsm = (float*)(sm + SHS);

    const int tid  = threadIdx.x;
    const int wm   = tid >> 5, lane = tid & 31;
    const int rs   = blockIdx.x * MB;
    const int j0   = wm * 16 + (lane >> 2);   // unit for d regs q0,q1 (q2,q3 -> j0+8)
    const int cA   = (lane & 3) * 2;

    const int  xm = tid >> 3, xf = tid & 7;
    const bool xth = tid < MB * FF;
    const bool gx  = xth && (rs + xm < BB);
    const float bof = bog[xf];
    const float* xrow = x   + (size_t)(rs + xm) * T * FF + xf;
    float*       orow = out + (size_t)(rs + xm) * T * FF + xf;

    for (int i = tid; i < 4608; i += NT) ((u32*)(sm + SBF))[i] = 0;   // B frags
    for (int i = tid; i < H * FF; i += NT) wosm[i] = Wo[i];
    __syncthreads();                          // zero before 1.0 slots
    if (tid < 64) {                           // bias rows: B_hi = 1.0, both buffers
        int b2 = tid >> 5, k = 8 + ((tid >> 4) & 1), n = tid & 15;
        bfu[bslot(b2 * 2, 8, k, n)] = 0x3F80;
    }
    if (gx) write_x(bfu, 0, xf, xm, xrow[0]);

    float cst[2][4];                          // [unit u][cc] — 8 independent states
    #pragma unroll
    for (int u = 0; u < 2; u++)
        #pragma unroll
        for (int c = 0; c < 4; c++) cst[u][c] = 0.f;
    int buf = 0;

    for (int phase = 0; phase < 2; phase++) {
        const bool dec = (phase == 1);
        const uint4* gafh = g_AFhi + phase * 9216;
        const uint4* gafl = g_AFlo + phase * 9216;

        for (int i = tid; i < 9216; i += NT) afh[i] = gafh[i];        // A_hi -> smem
        if (dec && gx) write_x(bfu, buf, xf, xm, xrow[(size_t)(T - 1) * FF]);  // y0
        __syncthreads();

        for (int t = 0; t < T; t++) {
            // ---- z = [U;W;b]^T [h;x;1] : 216 HMMA/warp, D in regs ----
            float d[4][2][4];
            #pragma unroll
            for (int g = 0; g < 4; g++)
                #pragma unroll
                for (int nt = 0; nt < 2; nt++)
                    #pragma unroll
                    for (int q = 0; q < 4; q++) d[g][nt][q] = 0.f;

            uint4 ah[4], alo[4], ahn[4], alon[4];
            #pragma unroll
            for (int g = 0; g < 4; g++) {
                ah[g]  = afh[((wm * NKC) * 4 + g) * 32 + lane];
                alo[g] = gafl[((wm * NKC) * 4 + g) * 32 + lane];
            }
            uint4 bh = bfr[((buf * 2 + 0) * NKC) * 32 + lane];
            uint4 bl = bfr[((buf * 2 + 1) * NKC) * 32 + lane];

            #pragma unroll
            for (int kc = 0; kc < NKC; kc++) {
                uint4 bhn, bln;
                if (kc + 1 < NKC) {
                    #pragma unroll
                    for (int g = 0; g < 4; g++) {
                        ahn[g]  = afh[((wm * NKC + kc + 1) * 4 + g) * 32 + lane];
                        alon[g] = gafl[((wm * NKC + kc + 1) * 4 + g) * 32 + lane];
                    }
                    bhn = bfr[((buf * 2 + 0) * NKC + kc + 1) * 32 + lane];
                    bln = bfr[((buf * 2 + 1) * NKC + kc + 1) * 32 + lane];
                }
                #pragma unroll
                for (int g = 0; g < 4; g++) {
                    mma16816(d[g][0], ah[g], bh.x, bh.y);      // hi * hi
                    mma16816(d[g][1], ah[g], bh.z, bh.w);
                    mma16816(d[g][0], ah[g], bl.x, bl.y);      // hi * lo
                    mma16816(d[g][1], ah[g], bl.z, bl.w);
                    mma16816(d[g][0], alo[g], bh.x, bh.y);     // lo * hi
                    mma16816(d[g][1], alo[g], bh.z, bh.w);
                }
                if (kc + 1 < NKC) {
                    #pragma unroll
                    for (int g = 0; g < 4; g++) { ah[g] = ahn[g]; alo[g] = alon[g]; }
                    bh = bhn; bl = bln;
                }
            }

            // ---- gates straight from accumulators; scatter h into B(nbuf) ----
            const int nbuf = buf ^ 1;
            #pragma unroll
            for (int u = 0; u < 2; u++) {
                const int j  = j0 + u * 8;
                const int kk = j & 15;
                const int tb = (kk >> 1) & 3, regB = kk >> 3, bitB = kk & 1;
                #pragma unroll
                for (int cc = 0; cc < 4; cc++) {
                    const int nt = cc >> 1, off = cc & 1;
                    const int n  = cA + nt * 8 + off;
                    const int q  = u * 2 + off;
                    float zi = d[0][nt][q];
                    float zf = d[1][nt][q];
                    float zg = d[2][nt][q];
                    float zo = d[3][nt][q];
                    float di = 1.f + ex2f(-L2E * zi);
                    float df = 1.f + ex2f(-L2E * zf);
                    float r  = rcpf(di * df);
                    float si = r * df, sf = r * di;
                    float dg = 1.f + ex2f(2.f * L2E * zg);
                    float dd = 1.f + ex2f(-L2E * zo);
                    float r2 = rcpf(dg * dd);
                    float tg = fmaf(-2.f, r2 * dd, 1.f);
                    float so = r2 * dg;
                    float cn = fmaf(sf, cst[u][cc], si * tg);
                    cst[u][cc] = cn;
                    float dc = 1.f + ex2f(2.f * L2E * cn);
                    float hv = so * fmaf(-2.f, rcpf(dc), 1.f);
                    if (n < MB) {
                        const int laneB = (n & 7) * 4 + tb, ntB = n >> 3;
                        u16 hb = bf16bits(hv);
                        u16 lb = bf16bits(hv - bf16val(hb));
                        bfu[((((nbuf * 2 + 0) * NKC + wm) * 32 + laneB) << 3) + ((ntB * 2 + regB) << 1) + bitB] = hb;
                        bfu[((((nbuf * 2 + 1) * NKC + wm) * 32 + laneB) << 3) + ((ntB * 2 + regB) << 1) + bitB] = lb;
                        if (dec) hsm[j * 18 + n] = hv;
                    }
                }
            }

            if (!dec) {
                if (gx && t + 1 < T)    // prefetch next x straight into B(nbuf)
                    write_x(bfu, nbuf, xf, xm, xrow[(size_t)(t + 1) * FF]);
            } else {
                __syncthreads();        // hsm complete
                if (xth) {
                    float a = 0.f, b2 = 0.f;
                    #pragma unroll 8
                    for (int k = 0; k < H; k += 2) {
                        a  = fmaf(hsm[(k    ) * 18 + xm], wosm[(k    ) * FF + xf], a);
                        b2 = fmaf(hsm[(k + 1) * 18 + xm], wosm[(k + 1) * FF + xf], b2);
                    }
                    float y = fmaxf(bof + a + b2, 0.f);
                    if (gx) {
                        orow[(size_t)t * FF] = y;
                        write_x(bfu, nbuf, xf, xm, y);
                    }
                }
            }
            __syncthreads();            // B(nbuf) ready for next step
            buf ^= 1;
        }
    }
}

extern "C" void kernel_launch(void* const* d_in, const int* in_sizes, int n_in,
                              void* d_out, int out_size)
{
    const float* x  = (const float*)d_in[0];
    const float* We = (const float*)d_in[1];
    const float* Ue = (const float*)d_in[2];
    const float* be = (const float*)d_in[3];
    const float* Wd = (const float*)d_in[4];
    const float* Ud = (const float*)d_in[5];
    const float* bd = (const float*)d_in[6];
    const float* Wo = (const float*)d_in[7];
    const float* bo = (const float*)d_in[8];
    float* out = (float*)d_out;

    const int T = in_sizes[0] / (BB * FF);

    prep_kernel<<<(2 * 9216 + 255) / 256, 256>>>(Ue, Ud, We, Wd, be, bd);

    cudaFuncSetAttribute(lstm_mma_kernel,
                         cudaFuncAttributeMaxDynamicSharedMemorySize, SMEM_BYTES);
    lstm_mma_kernel<<<(BB + MB - 1) / MB, NT, SMEM_BYTES>>>(x, Wo, bo, out, T);
}